// round 4
// baseline (speedup 1.0000x reference)
#include <cuda_runtime.h>
#include <cuda_fp16.h>
#include <math.h>

// ---------------------------------------------------------------------------
// InteractionBlock (SchNet):
//   W(e) = gauss(e) @ Wf2 + bf2   -> 5121-row fp16 LUT, linear interp (fp32 math)
//   rf   = r @ Wa                 -> fp16 (consumed only by edge kernel)
//   acc  = segment_sum(rf[src] * W(e), dst)   (red.global.add.v4.f32)
//   out  = ssp(acc @ W1 + b1) @ W2 + b2       (fp32 GEMMs, f32x2 FFMA pairs)
// ---------------------------------------------------------------------------

#define NF 128
#define N_GAUSS 64
#define TAB 5121                 // step = 5/5120 = 1/1024
#define MAX_N 50048

static __device__ __half g_rf_h   [MAX_N * NF];
static __device__ float  g_acc    [MAX_N * NF];
static __device__ float  g_h      [MAX_N * NF];
static __device__ __half g_table_h[TAB * NF];

__device__ __forceinline__ float ssp(float x) {
    float ax = fabsf(x);
    float sp = fmaxf(x, 0.0f) + log1pf(__expf(-ax));
    return sp - 0.69314718055994530942f;
}

// packed 2-wide fp32 FMA: d = a*b + d  (lanewise on 2x fp32 in a 64-bit pair)
__device__ __forceinline__ void ffma2(unsigned long long& d,
                                      unsigned long long a,
                                      unsigned long long b) {
    asm("fma.rn.f32x2 %0, %1, %2, %0;" : "+l"(d) : "l"(a), "l"(b));
}

// ---------------------------------------------------------------------------
// LUT build: table[i][f] = bf2[f] + sum_k exp(coeff*(i*h - o_k)^2) * Wf2[k][f]
// Only the ~13 gaussians within 6 sigma contribute (> 1.5e-8).
// ---------------------------------------------------------------------------
__global__ void build_table_kernel(const float* __restrict__ Wf2,
                                   const float* __restrict__ bf2) {
    const float WIDTH = 5.0f / 63.0f;
    const float COEFF = -0.5f / (WIDTH * WIDTH);
    const float HSTEP = 1.0f / 1024.0f;

    int f = threadIdx.x;
    int i = blockIdx.x;
    float ev = (float)i * HSTEP;
    int kc = (int)(ev / WIDTH);
    int k0 = max(0, kc - 6);
    int k1 = min(N_GAUSS - 1, kc + 7);
    float acc = bf2[f];
    for (int k = k0; k <= k1; k++) {
        float d = ev - (float)k * WIDTH;
        acc += __expf(COEFF * d * d) * Wf2[k * NF + f];
    }
    g_table_h[i * NF + f] = __float2half_rn(acc);
}

__global__ void zero_acc_kernel(int n4) {
    int i = blockIdx.x * blockDim.x + threadIdx.x;
    if (i < n4) ((float4*)g_acc)[i] = make_float4(0.f, 0.f, 0.f, 0.f);
}

// ---------------------------------------------------------------------------
// Edge kernel: 4 edges per warp. All 12 data loads issued before any use
// (4x MLP on the L2-latency chain). fp16 LUT + fp16 rf, fp32 math + red.v4.
// ---------------------------------------------------------------------------
__global__ void edge_kernel(const float* __restrict__ e,
                            const int4*  __restrict__ a2,  // 2 edges per int4
                            int E) {
    int gid  = blockIdx.x * blockDim.x + threadIdx.x;
    int warp = gid >> 5;
    int lane = threadIdx.x & 31;
    int base = warp * 4;
    if (base >= E) return;

    // metadata: 1 + 2 broadcast vector loads
    float4 ev4 = *(const float4*)(e + base);
    int4 aa = a2[warp * 2];       // (dst0,src0,dst1,src1)
    int4 ab = a2[warp * 2 + 1];   // (dst2,src2,dst3,src3)

    float ev[4] = {ev4.x, ev4.y, ev4.z, ev4.w};
    int  dst[4] = {aa.x, aa.z, ab.x, ab.z};
    int  src[4] = {aa.y, aa.w, ab.y, ab.w};

    uint2 w0[4], w1[4], rf[4];
    float fr[4];
#pragma unroll
    for (int j = 0; j < 4; j++) {
        float u = ev[j] * 1024.0f;
        int   i = (int)u;
        i = max(0, min(i, TAB - 2));
        fr[j] = u - (float)i;
        const __half* trow = g_table_h + (size_t)i * NF + lane * 4;
        w0[j] = *(const uint2*)trow;
        w1[j] = *(const uint2*)(trow + NF);
        rf[j] = *(const uint2*)(g_rf_h + (size_t)src[j] * NF + lane * 4);
    }

#pragma unroll
    for (int j = 0; j < 4; j++) {
        float2 w0a = __half22float2(*reinterpret_cast<__half2*>(&w0[j].x));
        float2 w0b = __half22float2(*reinterpret_cast<__half2*>(&w0[j].y));
        float2 w1a = __half22float2(*reinterpret_cast<__half2*>(&w1[j].x));
        float2 w1b = __half22float2(*reinterpret_cast<__half2*>(&w1[j].y));
        float2 rfa = __half22float2(*reinterpret_cast<__half2*>(&rf[j].x));
        float2 rfb = __half22float2(*reinterpret_cast<__half2*>(&rf[j].y));

        float4 v;
        v.x = rfa.x * fmaf(fr[j], w1a.x - w0a.x, w0a.x);
        v.y = rfa.y * fmaf(fr[j], w1a.y - w0a.y, w0a.y);
        v.z = rfb.x * fmaf(fr[j], w1b.x - w0b.x, w0b.x);
        v.w = rfb.y * fmaf(fr[j], w1b.y - w0b.y, w0b.y);

        float* dp = g_acc + (size_t)dst[j] * NF + lane * 4;
        asm volatile("red.global.add.v4.f32 [%0], {%1, %2, %3, %4};"
                     :: "l"(dp), "f"(v.x), "f"(v.y), "f"(v.z), "f"(v.w)
                     : "memory");
    }
}

// ---------------------------------------------------------------------------
// SGEMM v3: C[N,128] = act(A[N,128] @ B[128,128] (+ bias))
// 64x128 block tile, BK=16, 256 threads, 8x4 microtile.
// Row-pair f32x2: A in smem column-major (LDS.64 -> natural row pair),
// B duplicated (b,b) float2.  Inner loop: 4 LDS.64 + 2 LDS.128 + 16 FFMA2.
// Grid = ceil(tiles/2) blocks, each block does exactly 2 tiles (one wave).
// ---------------------------------------------------------------------------
template <int ACT, bool HAS_BIAS, typename OutT>
__global__ void __launch_bounds__(256)
gemm128_v3(const float* __restrict__ A,
           const float* __restrict__ B,
           const float* __restrict__ bias,
           OutT* __restrict__ C, int N, int numTiles) {
    __shared__ float  As[16][66];     // col-major [k][row], stride 66 (bank-exact)
    __shared__ float2 Bs2[16][128];   // [k][col] duplicated (b,b)

    int tid = threadIdx.x;
    int tx  = tid & 31;      // cols tx*4 .. tx*4+3
    int ty  = tid >> 5;      // rows ty*8 .. ty*8+7  (constant within warp)

    for (int t = 0; t < 2; t++) {
        int tile = blockIdx.x + t * gridDim.x;
        if (tile >= numTiles) break;
        int rowBase = tile * 64;

        unsigned long long acc[4][4];   // [row-pair p][col c] = (C[2p][c], C[2p+1][c])
#pragma unroll
        for (int p = 0; p < 4; p++)
#pragma unroll
            for (int c = 0; c < 4; c++) acc[p][c] = 0ull;

#pragma unroll
        for (int kt = 0; kt < 8; kt++) {
            // A tile 64x16 -> col-major As[k][row]; 1 float4 per thread.
            {
                int ar  = tid >> 2;           // 0..63
                int ac4 = tid & 3;            // 0..3
                int grow = rowBase + ar;
                float4 av = make_float4(0.f, 0.f, 0.f, 0.f);
                if (grow < N)
                    av = *(const float4*)(A + (size_t)grow * NF + kt * 16 + ac4 * 4);
                As[ac4 * 4 + 0][ar] = av.x;
                As[ac4 * 4 + 1][ar] = av.y;
                As[ac4 * 4 + 2][ar] = av.z;
                As[ac4 * 4 + 3][ar] = av.w;
            }
            // B tile 16x128 -> duplicated float2; 8 lane-strided scalar loads.
#pragma unroll
            for (int j = 0; j < 2; j++) {
                int row = (tid >> 5) + 8 * j;         // 0..15
#pragma unroll
                for (int q = 0; q < 4; q++) {
                    int col = (tid & 31) + 32 * q;    // 0..127
                    float bv = B[(size_t)(kt * 16 + row) * NF + col];
                    Bs2[row][col] = make_float2(bv, bv);
                }
            }
            __syncthreads();

#pragma unroll
            for (int k = 0; k < 16; k++) {
                unsigned long long ap[4];
#pragma unroll
                for (int p = 0; p < 4; p++)
                    ap[p] = *(const unsigned long long*)&As[k][ty * 8 + 2 * p];
                ulonglong2 b01 = *(const ulonglong2*)&Bs2[k][tx * 4];
                ulonglong2 b23 = *(const ulonglong2*)&Bs2[k][tx * 4 + 2];
#pragma unroll
                for (int p = 0; p < 4; p++) {
                    ffma2(acc[p][0], ap[p], b01.x);
                    ffma2(acc[p][1], ap[p], b01.y);
                    ffma2(acc[p][2], ap[p], b23.x);
                    ffma2(acc[p][3], ap[p], b23.y);
                }
            }
            __syncthreads();
        }

        // epilogue
        float bb[4] = {0.f, 0.f, 0.f, 0.f};
        if (HAS_BIAS) {
            float4 tb = *(const float4*)(bias + tx * 4);
            bb[0] = tb.x; bb[1] = tb.y; bb[2] = tb.z; bb[3] = tb.w;
        }

#pragma unroll
        for (int p = 0; p < 4; p++) {
            float2 f[4];
#pragma unroll
            for (int c = 0; c < 4; c++)
                f[c] = *reinterpret_cast<float2*>(&acc[p][c]);
#pragma unroll
            for (int half = 0; half < 2; half++) {
                int row = rowBase + ty * 8 + 2 * p + half;
                if (row >= N) continue;
                float o[4];
#pragma unroll
                for (int c = 0; c < 4; c++)
                    o[c] = (half ? f[c].y : f[c].x) + bb[c];
                if (ACT == 1) {
#pragma unroll
                    for (int c = 0; c < 4; c++) o[c] = ssp(o[c]);
                }
                if (sizeof(OutT) == 2) {
                    __half2* cp = (__half2*)((__half*)C + (size_t)row * NF + tx * 4);
                    cp[0] = __floats2half2_rn(o[0], o[1]);
                    cp[1] = __floats2half2_rn(o[2], o[3]);
                } else {
                    *(float4*)((float*)C + (size_t)row * NF + tx * 4)
                        = make_float4(o[0], o[1], o[2], o[3]);
                }
            }
        }
    }
}

// ---------------------------------------------------------------------------
// Launch
// ---------------------------------------------------------------------------
extern "C" void kernel_launch(void* const* d_in, const int* in_sizes, int n_in,
                              void* d_out, int out_size) {
    const float* r   = (const float*)d_in[0];
    const float* e   = (const float*)d_in[1];
    const float* Wf2 = (const float*)d_in[2];
    const float* bf2 = (const float*)d_in[3];
    const float* Wa  = (const float*)d_in[4];
    const float* W1  = (const float*)d_in[5];
    const float* b1  = (const float*)d_in[6];
    const float* W2  = (const float*)d_in[7];
    const float* b2  = (const float*)d_in[8];
    const int*   a   = (const int*)d_in[9];

    int N = in_sizes[0] / NF;     // 50000
    int E = in_sizes[1];          // 800000

    __half *p_rf_h;  float *p_acc, *p_h;
    cudaGetSymbolAddress((void**)&p_rf_h, g_rf_h);
    cudaGetSymbolAddress((void**)&p_acc,  g_acc);
    cudaGetSymbolAddress((void**)&p_h,    g_h);

    // 1. Filter LUT (fp16, includes bf2)
    build_table_kernel<<<TAB, 128>>>(Wf2, bf2);

    // 2. Zero scatter accumulator
    int n4 = (N * NF) / 4;
    zero_acc_kernel<<<(n4 + 255) / 256, 256>>>(n4);

    // 3. rf = r @ Wa  (fp16 out)
    int numTiles = (N + 63) / 64;
    int gb = (numTiles + 1) / 2;
    gemm128_v3<0, false, __half><<<gb, 256>>>(r, Wa, nullptr, p_rf_h, N, numTiles);

    // 4. Edge gather-modulate-scatter (4 edges per warp)
    int warps   = (E + 3) / 4;
    int eblocks = (warps + 7) / 8;
    edge_kernel<<<eblocks, 256>>>(e, (const int4*)a, E);

    // 5. h = ssp(acc @ W1 + b1)
    gemm128_v3<1, true, float><<<gb, 256>>>(p_acc, W1, b1, p_h, N, numTiles);

    // 6. out = h @ W2 + b2
    gemm128_v3<0, true, float><<<gb, 256>>>(p_h, W2, b2, (float*)d_out, N, numTiles);
}

// round 5
// speedup vs baseline: 1.0055x; 1.0055x over previous
#include <cuda_runtime.h>
#include <cuda_fp16.h>
#include <math.h>

// ---------------------------------------------------------------------------
// InteractionBlock (SchNet):
//   W(e) = gauss(e) @ Wf2 + bf2   -> 5121-row fp16 LUT, linear interp (fp32 math)
//   rf   = r @ Wa                 -> fp16 (consumed only by edge kernel)
//   acc  = segment_sum(rf[src] * W(e), dst)   (red.global.add.v4.f32)
//   out  = ssp(acc @ W1 + b1) @ W2 + b2       (fp32 GEMMs, f32x2 FFMA pairs)
// ---------------------------------------------------------------------------

#define NF 128
#define N_GAUSS 64
#define TAB 5121                 // step = 5/5120 = 1/1024
#define MAX_N 50048

static __device__ __half g_rf_h   [MAX_N * NF];
static __device__ float  g_acc    [MAX_N * NF];
static __device__ float  g_h      [MAX_N * NF];
static __device__ __half g_table_h[TAB * NF];

__device__ __forceinline__ float ssp(float x) {
    float ax = fabsf(x);
    float sp = fmaxf(x, 0.0f) + log1pf(__expf(-ax));
    return sp - 0.69314718055994530942f;
}

// packed 2-wide fp32 FMA: d = a*b + d  (lanewise on 2x fp32 in a 64-bit pair)
__device__ __forceinline__ void ffma2(unsigned long long& d,
                                      unsigned long long a,
                                      unsigned long long b) {
    asm("fma.rn.f32x2 %0, %1, %2, %0;" : "+l"(d) : "l"(a), "l"(b));
}

// ---------------------------------------------------------------------------
// LUT build: table[i][f] = bf2[f] + sum_k exp(coeff*(i*h - o_k)^2) * Wf2[k][f]
// Only the ~13 gaussians within 6 sigma contribute (> 1.5e-8).
// ---------------------------------------------------------------------------
__global__ void build_table_kernel(const float* __restrict__ Wf2,
                                   const float* __restrict__ bf2) {
    const float WIDTH = 5.0f / 63.0f;
    const float COEFF = -0.5f / (WIDTH * WIDTH);
    const float HSTEP = 1.0f / 1024.0f;

    int f = threadIdx.x;
    int i = blockIdx.x;
    float ev = (float)i * HSTEP;
    int kc = (int)(ev / WIDTH);
    int k0 = max(0, kc - 6);
    int k1 = min(N_GAUSS - 1, kc + 7);
    float acc = bf2[f];
    for (int k = k0; k <= k1; k++) {
        float d = ev - (float)k * WIDTH;
        acc += __expf(COEFF * d * d) * Wf2[k * NF + f];
    }
    g_table_h[i * NF + f] = __float2half_rn(acc);
}

__global__ void zero_acc_kernel(int n4) {
    int i = blockIdx.x * blockDim.x + threadIdx.x;
    if (i < n4) ((float4*)g_acc)[i] = make_float4(0.f, 0.f, 0.f, 0.f);
}

// ---------------------------------------------------------------------------
// Edge kernel: 4 edges per warp. All 12 data loads issued before any use
// (4x MLP on the L2-latency chain). fp16 LUT + fp16 rf, fp32 math + red.v4.
// ---------------------------------------------------------------------------
__global__ void edge_kernel(const float* __restrict__ e,
                            const int4*  __restrict__ a2,  // 2 edges per int4
                            int E) {
    int gid  = blockIdx.x * blockDim.x + threadIdx.x;
    int warp = gid >> 5;
    int lane = threadIdx.x & 31;
    int base = warp * 4;
    if (base >= E) return;

    // metadata: 1 + 2 broadcast vector loads
    float4 ev4 = *(const float4*)(e + base);
    int4 aa = a2[warp * 2];       // (dst0,src0,dst1,src1)
    int4 ab = a2[warp * 2 + 1];   // (dst2,src2,dst3,src3)

    float ev[4] = {ev4.x, ev4.y, ev4.z, ev4.w};
    int  dst[4] = {aa.x, aa.z, ab.x, ab.z};
    int  src[4] = {aa.y, aa.w, ab.y, ab.w};

    uint2 w0[4], w1[4], rf[4];
    float fr[4];
#pragma unroll
    for (int j = 0; j < 4; j++) {
        float u = ev[j] * 1024.0f;
        int   i = (int)u;
        i = max(0, min(i, TAB - 2));
        fr[j] = u - (float)i;
        const __half* trow = g_table_h + (size_t)i * NF + lane * 4;
        w0[j] = *(const uint2*)trow;
        w1[j] = *(const uint2*)(trow + NF);
        rf[j] = *(const uint2*)(g_rf_h + (size_t)src[j] * NF + lane * 4);
    }

#pragma unroll
    for (int j = 0; j < 4; j++) {
        float2 w0a = __half22float2(*reinterpret_cast<__half2*>(&w0[j].x));
        float2 w0b = __half22float2(*reinterpret_cast<__half2*>(&w0[j].y));
        float2 w1a = __half22float2(*reinterpret_cast<__half2*>(&w1[j].x));
        float2 w1b = __half22float2(*reinterpret_cast<__half2*>(&w1[j].y));
        float2 rfa = __half22float2(*reinterpret_cast<__half2*>(&rf[j].x));
        float2 rfb = __half22float2(*reinterpret_cast<__half2*>(&rf[j].y));

        float4 v;
        v.x = rfa.x * fmaf(fr[j], w1a.x - w0a.x, w0a.x);
        v.y = rfa.y * fmaf(fr[j], w1a.y - w0a.y, w0a.y);
        v.z = rfb.x * fmaf(fr[j], w1b.x - w0b.x, w0b.x);
        v.w = rfb.y * fmaf(fr[j], w1b.y - w0b.y, w0b.y);

        float* dp = g_acc + (size_t)dst[j] * NF + lane * 4;
        asm volatile("red.global.add.v4.f32 [%0], {%1, %2, %3, %4};"
                     :: "l"(dp), "f"(v.x), "f"(v.y), "f"(v.z), "f"(v.w)
                     : "memory");
    }
}

// ---------------------------------------------------------------------------
// SGEMM v3: C[N,128] = act(A[N,128] @ B[128,128] (+ bias))
// 64x128 block tile, BK=16, 256 threads, 8x4 microtile.
// Row-pair f32x2: A in smem column-major (LDS.64 -> natural row pair),
// B duplicated (b,b) float2.  Inner loop: 4 LDS.64 + 2 LDS.128 + 16 FFMA2.
// Grid = ceil(tiles/2) blocks, each block does exactly 2 tiles (one wave).
// ---------------------------------------------------------------------------
template <int ACT, bool HAS_BIAS, typename OutT>
__global__ void __launch_bounds__(256)
gemm128_v3(const float* __restrict__ A,
           const float* __restrict__ B,
           const float* __restrict__ bias,
           OutT* __restrict__ C, int N, int numTiles) {
    __shared__ float  As[16][66];     // col-major [k][row], stride 66 (bank-exact)
    __shared__ float2 Bs2[16][128];   // [k][col] duplicated (b,b)

    int tid = threadIdx.x;
    int tx  = tid & 31;      // cols tx*4 .. tx*4+3
    int ty  = tid >> 5;      // rows ty*8 .. ty*8+7  (constant within warp)

    for (int t = 0; t < 2; t++) {
        int tile = blockIdx.x + t * gridDim.x;
        if (tile >= numTiles) break;
        int rowBase = tile * 64;

        unsigned long long acc[4][4];   // [row-pair p][col c] = (C[2p][c], C[2p+1][c])
#pragma unroll
        for (int p = 0; p < 4; p++)
#pragma unroll
            for (int c = 0; c < 4; c++) acc[p][c] = 0ull;

#pragma unroll
        for (int kt = 0; kt < 8; kt++) {
            // A tile 64x16 -> col-major As[k][row]; 1 float4 per thread.
            {
                int ar  = tid >> 2;           // 0..63
                int ac4 = tid & 3;            // 0..3
                int grow = rowBase + ar;
                float4 av = make_float4(0.f, 0.f, 0.f, 0.f);
                if (grow < N)
                    av = *(const float4*)(A + (size_t)grow * NF + kt * 16 + ac4 * 4);
                As[ac4 * 4 + 0][ar] = av.x;
                As[ac4 * 4 + 1][ar] = av.y;
                As[ac4 * 4 + 2][ar] = av.z;
                As[ac4 * 4 + 3][ar] = av.w;
            }
            // B tile 16x128 -> duplicated float2; 8 lane-strided scalar loads.
#pragma unroll
            for (int j = 0; j < 2; j++) {
                int row = (tid >> 5) + 8 * j;         // 0..15
#pragma unroll
                for (int q = 0; q < 4; q++) {
                    int col = (tid & 31) + 32 * q;    // 0..127
                    float bv = B[(size_t)(kt * 16 + row) * NF + col];
                    Bs2[row][col] = make_float2(bv, bv);
                }
            }
            __syncthreads();

#pragma unroll
            for (int k = 0; k < 16; k++) {
                unsigned long long ap[4];
#pragma unroll
                for (int p = 0; p < 4; p++)
                    ap[p] = *(const unsigned long long*)&As[k][ty * 8 + 2 * p];
                ulonglong2 b01 = *(const ulonglong2*)&Bs2[k][tx * 4];
                ulonglong2 b23 = *(const ulonglong2*)&Bs2[k][tx * 4 + 2];
#pragma unroll
                for (int p = 0; p < 4; p++) {
                    ffma2(acc[p][0], ap[p], b01.x);
                    ffma2(acc[p][1], ap[p], b01.y);
                    ffma2(acc[p][2], ap[p], b23.x);
                    ffma2(acc[p][3], ap[p], b23.y);
                }
            }
            __syncthreads();
        }

        // epilogue
        float bb[4] = {0.f, 0.f, 0.f, 0.f};
        if (HAS_BIAS) {
            float4 tb = *(const float4*)(bias + tx * 4);
            bb[0] = tb.x; bb[1] = tb.y; bb[2] = tb.z; bb[3] = tb.w;
        }

#pragma unroll
        for (int p = 0; p < 4; p++) {
            float2 f[4];
#pragma unroll
            for (int c = 0; c < 4; c++)
                f[c] = *reinterpret_cast<float2*>(&acc[p][c]);
#pragma unroll
            for (int half = 0; half < 2; half++) {
                int row = rowBase + ty * 8 + 2 * p + half;
                if (row >= N) continue;
                float o[4];
#pragma unroll
                for (int c = 0; c < 4; c++)
                    o[c] = (half ? f[c].y : f[c].x) + bb[c];
                if (ACT == 1) {
#pragma unroll
                    for (int c = 0; c < 4; c++) o[c] = ssp(o[c]);
                }
                if (sizeof(OutT) == 2) {
                    __half2* cp = (__half2*)((__half*)C + (size_t)row * NF + tx * 4);
                    cp[0] = __floats2half2_rn(o[0], o[1]);
                    cp[1] = __floats2half2_rn(o[2], o[3]);
                } else {
                    *(float4*)((float*)C + (size_t)row * NF + tx * 4)
                        = make_float4(o[0], o[1], o[2], o[3]);
                }
            }
        }
    }
}

// ---------------------------------------------------------------------------
// Launch
// ---------------------------------------------------------------------------
extern "C" void kernel_launch(void* const* d_in, const int* in_sizes, int n_in,
                              void* d_out, int out_size) {
    const float* r   = (const float*)d_in[0];
    const float* e   = (const float*)d_in[1];
    const float* Wf2 = (const float*)d_in[2];
    const float* bf2 = (const float*)d_in[3];
    const float* Wa  = (const float*)d_in[4];
    const float* W1  = (const float*)d_in[5];
    const float* b1  = (const float*)d_in[6];
    const float* W2  = (const float*)d_in[7];
    const float* b2  = (const float*)d_in[8];
    const int*   a   = (const int*)d_in[9];

    int N = in_sizes[0] / NF;     // 50000
    int E = in_sizes[1];          // 800000

    __half *p_rf_h;  float *p_acc, *p_h;
    cudaGetSymbolAddress((void**)&p_rf_h, g_rf_h);
    cudaGetSymbolAddress((void**)&p_acc,  g_acc);
    cudaGetSymbolAddress((void**)&p_h,    g_h);

    // 1. Filter LUT (fp16, includes bf2)
    build_table_kernel<<<TAB, 128>>>(Wf2, bf2);

    // 2. Zero scatter accumulator
    int n4 = (N * NF) / 4;
    zero_acc_kernel<<<(n4 + 255) / 256, 256>>>(n4);

    // 3. rf = r @ Wa  (fp16 out)
    int numTiles = (N + 63) / 64;
    int gb = (numTiles + 1) / 2;
    gemm128_v3<0, false, __half><<<gb, 256>>>(r, Wa, nullptr, p_rf_h, N, numTiles);

    // 4. Edge gather-modulate-scatter (4 edges per warp)
    int warps   = (E + 3) / 4;
    int eblocks = (warps + 7) / 8;
    edge_kernel<<<eblocks, 256>>>(e, (const int4*)a, E);

    // 5. h = ssp(acc @ W1 + b1)
    gemm128_v3<1, true, float><<<gb, 256>>>(p_acc, W1, b1, p_h, N, numTiles);

    // 6. out = h @ W2 + b2
    gemm128_v3<0, true, float><<<gb, 256>>>(p_h, W2, b2, (float*)d_out, N, numTiles);
}

// round 7
// speedup vs baseline: 1.2707x; 1.2637x over previous
#include <cuda_runtime.h>
#include <cuda_fp16.h>
#include <math.h>

// ---------------------------------------------------------------------------
// InteractionBlock (SchNet):
//   W(e) = gauss(e) @ Wf2 + bf2   -> 5121-row fp16 LUT, linear interp (fp32 math)
//   rf   = r @ Wa                 -> fp16 (consumed only by edge kernel)
//   acc  = segment_sum(rf[src] * W(e), dst)   (red.global.add.v4.f32)
//   out  = ssp(acc @ W1 + b1) @ W2 + b2       (fp32 GEMMs, column-pair f32x2)
// ---------------------------------------------------------------------------

#define NF 128
#define N_GAUSS 64
#define TAB 5121                 // step = 5/5120 = 1/1024
#define MAX_N 50048

static __device__ __half g_rf_h   [MAX_N * NF];
static __device__ float  g_acc    [MAX_N * NF];
static __device__ float  g_h      [MAX_N * NF];
static __device__ __half g_table_h[TAB * NF];

__device__ __forceinline__ float ssp(float x) {
    float ax = fabsf(x);
    float sp = fmaxf(x, 0.0f) + log1pf(__expf(-ax));
    return sp - 0.69314718055994530942f;
}

// packed 2-wide fp32 FMA: d = a*b + d
__device__ __forceinline__ void ffma2(unsigned long long& d,
                                      unsigned long long a,
                                      unsigned long long b) {
    asm("fma.rn.f32x2 %0, %1, %2, %0;" : "+l"(d) : "l"(a), "l"(b));
}

// ---------------------------------------------------------------------------
// LUT build (only ~13 gaussians within 6 sigma contribute)
// ---------------------------------------------------------------------------
__global__ void build_table_kernel(const float* __restrict__ Wf2,
                                   const float* __restrict__ bf2) {
    const float WIDTH = 5.0f / 63.0f;
    const float COEFF = -0.5f / (WIDTH * WIDTH);
    const float HSTEP = 1.0f / 1024.0f;

    int f = threadIdx.x;
    int i = blockIdx.x;
    float ev = (float)i * HSTEP;
    int kc = (int)(ev / WIDTH);
    int k0 = max(0, kc - 6);
    int k1 = min(N_GAUSS - 1, kc + 7);
    float acc = bf2[f];
    for (int k = k0; k <= k1; k++) {
        float d = ev - (float)k * WIDTH;
        acc += __expf(COEFF * d * d) * Wf2[k * NF + f];
    }
    g_table_h[i * NF + f] = __float2half_rn(acc);
}

__global__ void zero_acc_kernel(int n4) {
    int i = blockIdx.x * blockDim.x + threadIdx.x;
    if (i < n4) ((float4*)g_acc)[i] = make_float4(0.f, 0.f, 0.f, 0.f);
}

// ---------------------------------------------------------------------------
// Edge kernel: 4 edges per warp, all loads issued before any use (R5, proven).
// ---------------------------------------------------------------------------
__global__ void edge_kernel(const float* __restrict__ e,
                            const int4*  __restrict__ a2,  // 2 edges per int4
                            int E) {
    int gid  = blockIdx.x * blockDim.x + threadIdx.x;
    int warp = gid >> 5;
    int lane = threadIdx.x & 31;
    int base = warp * 4;
    if (base >= E) return;

    float4 ev4 = *(const float4*)(e + base);
    int4 aa = a2[warp * 2];
    int4 ab = a2[warp * 2 + 1];

    float ev[4] = {ev4.x, ev4.y, ev4.z, ev4.w};
    int  dst[4] = {aa.x, aa.z, ab.x, ab.z};
    int  src[4] = {aa.y, aa.w, ab.y, ab.w};

    uint2 w0[4], w1[4], rf[4];
    float fr[4];
#pragma unroll
    for (int j = 0; j < 4; j++) {
        float u = ev[j] * 1024.0f;
        int   i = (int)u;
        i = max(0, min(i, TAB - 2));
        fr[j] = u - (float)i;
        const __half* trow = g_table_h + (size_t)i * NF + lane * 4;
        w0[j] = *(const uint2*)trow;
        w1[j] = *(const uint2*)(trow + NF);
        rf[j] = *(const uint2*)(g_rf_h + (size_t)src[j] * NF + lane * 4);
    }

#pragma unroll
    for (int j = 0; j < 4; j++) {
        float2 w0a = __half22float2(*reinterpret_cast<__half2*>(&w0[j].x));
        float2 w0b = __half22float2(*reinterpret_cast<__half2*>(&w0[j].y));
        float2 w1a = __half22float2(*reinterpret_cast<__half2*>(&w1[j].x));
        float2 w1b = __half22float2(*reinterpret_cast<__half2*>(&w1[j].y));
        float2 rfa = __half22float2(*reinterpret_cast<__half2*>(&rf[j].x));
        float2 rfb = __half22float2(*reinterpret_cast<__half2*>(&rf[j].y));

        float4 v;
        v.x = rfa.x * fmaf(fr[j], w1a.x - w0a.x, w0a.x);
        v.y = rfa.y * fmaf(fr[j], w1a.y - w0a.y, w0a.y);
        v.z = rfb.x * fmaf(fr[j], w1b.x - w0b.x, w0b.x);
        v.w = rfb.y * fmaf(fr[j], w1b.y - w0b.y, w0b.y);

        float* dp = g_acc + (size_t)dst[j] * NF + lane * 4;
        asm volatile("red.global.add.v4.f32 [%0], {%1, %2, %3, %4};"
                     :: "l"(dp), "f"(v.x), "f"(v.y), "f"(v.z), "f"(v.w)
                     : "memory");
    }
}

// ---------------------------------------------------------------------------
// SGEMM v4: C[N,128] = act(A[N,128] @ B[128,128] (+ bias))
// R2-v1 tiling (64x128, BK=32, 256 thr, 8 rows x 4 cols/thread) with
// column-pair f32x2 math.  B smem layout/loads IDENTICAL to v1 (LDS.128
// conflict-free); only A is stored duplicated (a,a) for 64-bit broadcast.
// Inner loop per k: 8x LDS.64(bcast) + 1x LDS.128 + 16x FFMA2.
// Persistent grid (296 blocks) strided over tiles -> balanced waves.
// ---------------------------------------------------------------------------
template <int ACT, bool HAS_BIAS, typename OutT>
__global__ void __launch_bounds__(256)
gemm128_v4(const float* __restrict__ A,
           const float* __restrict__ B,
           const float* __restrict__ bias,
           OutT* __restrict__ C, int N, int numTiles) {
    __shared__ float2 As2[64][33];    // [row][k] duplicated (a,a); pad k-dim
    __shared__ float  Bs[32][128];    // [k][col]

    int tid = threadIdx.x;
    int tx  = tid & 31;      // cols tx*4 .. tx*4+3
    int ty  = tid >> 5;      // rows ty*8 .. ty*8+7

    for (int tile = blockIdx.x; tile < numTiles; tile += gridDim.x) {
        int rowBase = tile * 64;

        unsigned long long acc[8][2];   // [row i][col pair j]
#pragma unroll
        for (int i = 0; i < 8; i++) { acc[i][0] = 0ull; acc[i][1] = 0ull; }

#pragma unroll
        for (int kt = 0; kt < 4; kt++) {
            // A tile: 64 rows x 32 k. 512 float4 loads; 2 per thread.
#pragma unroll
            for (int j = 0; j < 2; j++) {
                int idx = tid + j * 256;          // 0..511
                int ar  = idx >> 3;               // 0..63
                int ac4 = idx & 7;                // 0..7
                int grow = rowBase + ar;
                float4 av = make_float4(0.f, 0.f, 0.f, 0.f);
                if (grow < N)
                    av = *(const float4*)(A + (size_t)grow * NF + kt * 32 + ac4 * 4);
                As2[ar][ac4 * 4 + 0] = make_float2(av.x, av.x);
                As2[ar][ac4 * 4 + 1] = make_float2(av.y, av.y);
                As2[ar][ac4 * 4 + 2] = make_float2(av.z, av.z);
                As2[ar][ac4 * 4 + 3] = make_float2(av.w, av.w);
            }
            // B tile: 32 k x 128 cols. 1024 float4; 4 per thread (same as v1).
#pragma unroll
            for (int j = 0; j < 4; j++) {
                int idx = tid + j * 256;          // 0..1023
                int br  = idx >> 5;               // 0..31
                int bc4 = idx & 31;               // 0..31
                float4 bv = *(const float4*)(B + (size_t)(kt * 32 + br) * NF + bc4 * 4);
                *(float4*)&Bs[br][bc4 * 4] = bv;
            }
            __syncthreads();

#pragma unroll
            for (int k = 0; k < 32; k++) {
                ulonglong2 b = *(const ulonglong2*)&Bs[k][tx * 4]; // (b0,b1),(b2,b3)
#pragma unroll
                for (int i = 0; i < 8; i++) {
                    unsigned long long av =
                        *(const unsigned long long*)&As2[ty * 8 + i][k];
                    ffma2(acc[i][0], av, b.x);
                    ffma2(acc[i][1], av, b.y);
                }
            }
            __syncthreads();
        }

        // epilogue: cols tx*4..tx*4+3, rows rowBase+ty*8..+7
        float4 bb = make_float4(0.f, 0.f, 0.f, 0.f);
        if (HAS_BIAS) bb = *(const float4*)(bias + tx * 4);

#pragma unroll
        for (int i = 0; i < 8; i++) {
            int row = rowBase + ty * 8 + i;
            if (row >= N) continue;
            float2 p0 = *reinterpret_cast<float2*>(&acc[i][0]);
            float2 p1 = *reinterpret_cast<float2*>(&acc[i][1]);
            float o[4] = { p0.x + bb.x, p0.y + bb.y, p1.x + bb.z, p1.y + bb.w };
            if (ACT == 1) {
#pragma unroll
                for (int c = 0; c < 4; c++) o[c] = ssp(o[c]);
            }
            if (sizeof(OutT) == 2) {
                __half2* cp = (__half2*)((__half*)C + (size_t)row * NF + tx * 4);
                cp[0] = __floats2half2_rn(o[0], o[1]);
                cp[1] = __floats2half2_rn(o[2], o[3]);
            } else {
                *(float4*)((float*)C + (size_t)row * NF + tx * 4)
                    = make_float4(o[0], o[1], o[2], o[3]);
            }
        }
    }
}

// ---------------------------------------------------------------------------
// Launch
// ---------------------------------------------------------------------------
extern "C" void kernel_launch(void* const* d_in, const int* in_sizes, int n_in,
                              void* d_out, int out_size) {
    const float* r   = (const float*)d_in[0];
    const float* e   = (const float*)d_in[1];
    const float* Wf2 = (const float*)d_in[2];
    const float* bf2 = (const float*)d_in[3];
    const float* Wa  = (const float*)d_in[4];
    const float* W1  = (const float*)d_in[5];
    const float* b1  = (const float*)d_in[6];
    const float* W2  = (const float*)d_in[7];
    const float* b2  = (const float*)d_in[8];
    const int*   a   = (const int*)d_in[9];

    int N = in_sizes[0] / NF;     // 50000
    int E = in_sizes[1];          // 800000

    __half *p_rf_h;  float *p_acc, *p_h;
    cudaGetSymbolAddress((void**)&p_rf_h, g_rf_h);
    cudaGetSymbolAddress((void**)&p_acc,  g_acc);
    cudaGetSymbolAddress((void**)&p_h,    g_h);

    // 1. Filter LUT (fp16, includes bf2)
    build_table_kernel<<<TAB, 128>>>(Wf2, bf2);

    // 2. Zero scatter accumulator
    int n4 = (N * NF) / 4;
    zero_acc_kernel<<<(n4 + 255) / 256, 256>>>(n4);

    int numTiles = (N + 63) / 64;              // 782
    int gb = numTiles < 296 ? numTiles : 296;  // persistent, balanced waves

    // 3. rf = r @ Wa  (fp16 out)
    gemm128_v4<0, false, __half><<<gb, 256>>>(r, Wa, nullptr, p_rf_h, N, numTiles);

    // 4. Edge gather-modulate-scatter (4 edges per warp)
    int warps   = (E + 3) / 4;
    int eblocks = (warps + 7) / 8;
    edge_kernel<<<eblocks, 256>>>(e, (const int4*)a, E);

    // 5. h = ssp(acc @ W1 + b1)
    gemm128_v4<1, true, float><<<gb, 256>>>(p_acc, W1, b1, p_h, N, numTiles);

    // 6. out = h @ W2 + b2
    gemm128_v4<0, true, float><<<gb, 256>>>(p_h, W2, b2, (float*)d_out, N, numTiles);
}